// round 4
// baseline (speedup 1.0000x reference)
#include <cuda_runtime.h>
#include <cuda_bf16.h>

// PosMLP: weights = q @ w_gen^T + b_gen  (per-query 65 scalars: w1y[16] interleaved
// with w1x[16], b1[16], w2[16], b2), then per-pixel 16-wide ReLU MLP over a 48x48
// grid of box-relative coordinates.
//
// Shapes (fixed by setup_inputs): B=2, Q=900, C=256, HIDDEN=16, H=W=48.
// Output: (2,900,48,48) f32.

#define CC   256
#define NW   65
#define HD   16
#define HH   48
#define WWW  48
#define QB   4            // queries per block
#define NTHREADS (QB * WWW)   // 192
#define NWARPS   (NTHREADS / 32)  // 6
#define NQ_TOTAL 1800     // B*Q

__global__ __launch_bounds__(NTHREADS) void posmlp_kernel(
    const float* __restrict__ queries,  // [1800][256]
    const float* __restrict__ pos,      // [1800][4]  (cx, cy, bw, bh)
    const float* __restrict__ w_gen,    // [65][256]
    const float* __restrict__ b_gen,    // [65]
    float* __restrict__ out)            // [1800][48][48]
{
    __shared__ float sh_q[QB][CC];      // 4 KB
    __shared__ float sh_wt[QB][NW];     // 1 KB

    const int tid   = threadIdx.x;
    const int qbase = blockIdx.x * QB;

    // ---- Load 4 query rows (contiguous 1024 floats) via float4 ----
    {
        const float4* qsrc = (const float4*)(queries + (size_t)qbase * CC);
        float4* qdst = (float4*)&sh_q[0][0];
        #pragma unroll
        for (int i = tid; i < QB * CC / 4; i += NTHREADS)
            qdst[i] = qsrc[i];
    }
    __syncthreads();

    // ---- Phase 1: weights[qi][n] = dot(q[qi], w_gen[n]) + b_gen[n] ----
    // One output row n per warp iteration; lane l owns channels l, l+32, ..., l+224.
    // w_gen reads: fully coalesced. sh_q reads: stride-1 across lanes (conflict-free).
    {
        const int warp = tid >> 5;
        const int lane = tid & 31;
        for (int n = warp; n < NW; n += NWARPS) {
            float wv[8];
            #pragma unroll
            for (int j = 0; j < 8; j++)
                wv[j] = w_gen[n * CC + 32 * j + lane];
            float bg = b_gen[n];
            #pragma unroll
            for (int qi = 0; qi < QB; qi++) {
                float s = 0.f;
                #pragma unroll
                for (int j = 0; j < 8; j++)
                    s = fmaf(wv[j], sh_q[qi][32 * j + lane], s);
                #pragma unroll
                for (int off = 16; off > 0; off >>= 1)
                    s += __shfl_xor_sync(0xffffffffu, s, off);
                if (lane == 0) sh_wt[qi][n] = s + bg;
            }
        }
    }
    __syncthreads();

    // ---- Phase 2: rasterize. Thread = (query qi, column w); loop over 48 rows. ----
    const int qi  = tid / WWW;          // 0..3
    const int w   = tid - qi * WWW;     // 0..47
    const int qid = qbase + qi;

    const float* wt = sh_wt[qi];
    const float cx = pos[qid * 4 + 0];
    const float cy = pos[qid * 4 + 1];
    const float bw = pos[qid * 4 + 2];
    const float bh = pos[qid * 4 + 3];

    const float rx     = ((w + 0.5f) * (1.0f / WWW) - cx) / bw;
    const float inv_bh = 1.0f / bh;

    // Fold rx*w1x + b1 into tw; keep w1y, tw, w2 in registers.
    float w1y[HD], tw[HD], w2[HD];
    #pragma unroll
    for (int k = 0; k < HD; k++) {
        w1y[k] = wt[2 * k];                               // weights[..., 2k]   (w1[...,0])
        tw[k]  = fmaf(rx, wt[2 * k + 1], wt[2 * HD + k]); // rx*w1x_k + b1_k
        w2[k]  = wt[3 * HD + k];
    }
    const float b2 = wt[4 * HD];

    float* obase = out + (size_t)qid * (HH * WWW) + w;
    #pragma unroll 2
    for (int h = 0; h < HH; h++) {
        const float ry = ((h + 0.5f) * (1.0f / HH) - cy) * inv_bh;
        float acc0 = b2, acc1 = 0.f;   // 2 chains for FMA-latency ILP
        #pragma unroll
        for (int k = 0; k < HD; k += 2) {
            float v0 = fmaf(ry, w1y[k],     tw[k]);
            float v1 = fmaf(ry, w1y[k + 1], tw[k + 1]);
            acc0 = fmaf(fmaxf(v0, 0.f), w2[k],     acc0);
            acc1 = fmaf(fmaxf(v1, 0.f), w2[k + 1], acc1);
        }
        obase[h * WWW] = acc0 + acc1;
    }
}

extern "C" void kernel_launch(void* const* d_in, const int* in_sizes, int n_in,
                              void* d_out, int out_size) {
    const float* queries = (const float*)d_in[0];
    const float* pos     = (const float*)d_in[1];
    const float* w_gen   = (const float*)d_in[2];
    const float* b_gen   = (const float*)d_in[3];
    float* out = (float*)d_out;

    posmlp_kernel<<<NQ_TOTAL / QB, NTHREADS>>>(queries, pos, w_gen, b_gen, out);
}